// round 1
// baseline (speedup 1.0000x reference)
#include <cuda_runtime.h>
#include <math.h>

#define NB 8
#define NT 512
#define NH 256
#define NM 4096
#define NW 256

// ---------------- scratch (device globals: no allocation allowed) ----------------
__device__ float g_h1[NB*NT*NH];     // after conv1+LN+relu
__device__ float g_h2[NB*NT*NH];     // after conv2+LN+relu
__device__ float g_m0[NB*NT];        // m before word rescale
__device__ float g_center[NB*NT];    // cumsum(m) - m/2
__device__ int   g_phs[NB*NW];       // phoneme start per (b,word)
__device__ int   g_phc[NB*NW];       // phoneme count per (b,word)
__device__ int   g_mels[NB*NW];      // mel start per (b,word)
__device__ int   g_melc[NB*NW];      // mel count per (b,word)

// ---------------- conv5 + channel-LN + relu ----------------
// in:(B,T,H) row-major. One block = (b, 32-t tile), 256 threads = out channels.
__global__ void conv_ln_relu(const float* __restrict__ in,
                             const float* __restrict__ mask,
                             const float* __restrict__ wgt,   // (O=256, I=256, K=5)
                             const float* __restrict__ bias,
                             const float* __restrict__ lng,
                             const float* __restrict__ lnb,
                             float* __restrict__ out)
{
    const int TT = 32;
    __shared__ float xs[TT + 4][NH];          // 36.9 KB, reused as ys after compute
    __shared__ float mu_s[TT], rs_s[TT];

    int b  = blockIdx.x / (NT / TT);
    int t0 = (blockIdx.x % (NT / TT)) * TT;
    int o  = threadIdx.x;

    for (int idx = o; idx < (TT + 4) * NH; idx += 256) {
        int tt = idx >> 8; int i = idx & 255;
        int t = t0 + tt - 2;
        float v = 0.0f;
        if (t >= 0 && t < NT) v = in[((size_t)b * NT + t) * NH + i] * mask[b * NT + t];
        xs[tt][i] = v;
    }
    __syncthreads();

    float acc[TT];
    float bo = bias[o];
    #pragma unroll
    for (int t = 0; t < TT; t++) acc[t] = bo;

    const float* wo = wgt + (size_t)o * (NH * 5);
    #pragma unroll 2
    for (int i = 0; i < NH; i++) {
        float w0 = wo[0], w1 = wo[1], w2 = wo[2], w3 = wo[3], w4 = wo[4];
        wo += 5;
        float x0 = xs[0][i], x1 = xs[1][i], x2 = xs[2][i], x3 = xs[3][i];
        #pragma unroll
        for (int t = 0; t < TT; t++) {
            float x4 = xs[t + 4][i];
            float s = x0 * w0;
            s = fmaf(x1, w1, s);
            s = fmaf(x2, w2, s);
            s = fmaf(x3, w3, s);
            s = fmaf(x4, w4, s);
            acc[t] += s;
            x0 = x1; x1 = x2; x2 = x3; x3 = x4;
        }
    }
    __syncthreads();                          // done reading xs

    float (*ys)[NH] = (float(*)[NH])xs;       // alias-reuse shared memory
    #pragma unroll
    for (int t = 0; t < TT; t++) ys[t][o] = acc[t];
    __syncthreads();

    // channel LayerNorm per (b,t): 8 warps each handle 4 rows
    int warp = o >> 5, lane = o & 31;
    for (int t = warp; t < TT; t += 8) {
        float s = 0.0f;
        for (int c = lane; c < NH; c += 32) s += ys[t][c];
        for (int off = 16; off; off >>= 1) s += __shfl_xor_sync(0xffffffffu, s, off);
        float mu = s * (1.0f / NH);
        float v = 0.0f;
        for (int c = lane; c < NH; c += 32) { float d = ys[t][c] - mu; v = fmaf(d, d, v); }
        for (int off = 16; off; off >>= 1) v += __shfl_xor_sync(0xffffffffu, v, off);
        v *= (1.0f / NH);
        if (lane == 0) { mu_s[t] = mu; rs_s[t] = 1.0f / sqrtf(v + 1e-4f); }
    }
    __syncthreads();

    float go = lng[o], b2 = lnb[o];
    #pragma unroll
    for (int t = 0; t < TT; t++) {
        float y = (ys[t][o] - mu_s[t]) * rs_s[t] * go + b2;
        out[((size_t)b * NT + t0 + t) * NH + o] = fmaxf(y, 0.0f);
    }
}

// ---------------- proj 1x1 + residual + gauss ch0 -> m0 ----------------
__global__ void proj_gauss(const float* __restrict__ x,
                           const float* __restrict__ mask,
                           const float* __restrict__ pw,   // (256,256)
                           const float* __restrict__ pb,
                           const float* __restrict__ gw,   // (2,256): ch0 = gw[0..255]
                           const float* __restrict__ gb)
{
    const int TT = 16;
    __shared__ float hs[TT][NH];
    __shared__ float red[256];

    int b  = blockIdx.x / (NT / TT);
    int t0 = (blockIdx.x % (NT / TT)) * TT;
    int o  = threadIdx.x;

    for (int idx = o; idx < TT * NH; idx += 256) {
        int tt = idx >> 8; int i = idx & 255;
        hs[tt][i] = g_h2[((size_t)b * NT + t0 + tt) * NH + i];
    }
    __syncthreads();

    float acc[TT];
    float pbo = pb[o];
    #pragma unroll
    for (int t = 0; t < TT; t++) acc[t] = pbo;

    const float* pwo = pw + (size_t)o * NH;
    for (int i = 0; i < NH; i++) {
        float w = pwo[i];
        #pragma unroll
        for (int t = 0; t < TT; t++) acc[t] = fmaf(w, hs[t][i], acc[t]);
    }

    float gwo = gw[o];   // channel 0 of gauss conv
    for (int t = 0; t < TT; t++) {
        float mt = mask[b * NT + t0 + t];
        float v = (x[((size_t)b * NT + t0 + t) * NH + o] + acc[t]) * mt;
        red[o] = gwo * v;
        __syncthreads();
        for (int s = 128; s > 0; s >>= 1) {
            if (o < s) red[o] += red[o + s];
            __syncthreads();
        }
        if (o == 0) {
            float g0 = red[0] + gb[0];
            g_m0[b * NT + t0 + t] = (fmaxf(g0, 0.0f) + 1.0f) * mt;
        }
        __syncthreads();
    }
}

// ---------------- word stats, rescale, cumsum -> center; writes m_word ----------------
__global__ void stats_kernel(const int* __restrict__ x2w,
                             const int* __restrict__ mel2w,
                             float* __restrict__ mword_out)
{
    int b = blockIdx.x;
    int tid = threadIdx.x;
    __shared__ int   cph[NW], cmel[NW], sph[NW], smel[NW];
    __shared__ float sc[NW];
    __shared__ float mbuf[NT];

    if (tid < NW) { cph[tid] = 0; cmel[tid] = 0; }
    __syncthreads();
    for (int p = tid; p < NT; p += 256) atomicAdd(&cph[x2w[b * NT + p] - 1], 1);
    for (int t = tid; t < NM; t += 256) atomicAdd(&cmel[mel2w[b * NM + t] - 1], 1);
    __syncthreads();
    if (tid == 0) { int s = 0; for (int w = 0; w < NW; w++) { sph[w]  = s; s += cph[w]; } }
    if (tid == 1) { int s = 0; for (int w = 0; w < NW; w++) { smel[w] = s; s += cmel[w]; } }
    __syncthreads();

    if (tid < NW) {
        int w = tid;
        int st = sph[w], c = cph[w];
        float s = 0.0f;
        for (int j = 0; j < c; j++) s += g_m0[b * NT + st + j];   // sequential, index order
        mword_out[b * NW + w] = s;
        sc[w] = (float)cmel[w] / (s + 1e-4f);
        g_phs[b * NW + w] = st;      g_phc[b * NW + w] = c;
        g_mels[b * NW + w] = smel[w]; g_melc[b * NW + w] = cmel[w];
    }
    __syncthreads();

    for (int p = tid; p < NT; p += 256) {
        int w = x2w[b * NT + p] - 1;
        float m0 = g_m0[b * NT + p];
        float d  = __fmul_rn(sc[w] - 1.0f, m0);   // replicate ref rounding: mul then add
        mbuf[p]  = __fadd_rn(m0, d);
    }
    __syncthreads();

    if (tid == 0) {
        float c = 0.0f;
        for (int p = 0; p < NT; p++) {
            c = __fadd_rn(c, mbuf[p]);            // sequential fp32 cumsum (as reference)
            float half = __fmul_rn(0.5f, mbuf[p]);
            g_center[b * NT + p] = __fadd_rn(c, -half);
        }
    }
}

// ---------------- matched rows: 1 warp per mel row ----------------
__global__ void attn_matched(const float* __restrict__ x,
                             const int* __restrict__ mel2w,
                             float* __restrict__ outA,
                             float* __restrict__ outW)
{
    __shared__ float wsm[8][64];
    int warp = threadIdx.x >> 5, lane = threadIdx.x & 31;
    int row = blockIdx.x * 8 + warp;
    int b = row >> 12;            // /4096
    int t = row & 4095;

    int w = mel2w[(size_t)b * NM + t] - 1;
    int cnt = g_phc[b * NW + w];
    if (cnt == 0) return;         // handled by attn_missing
    int lo = g_phs[b * NW + w];
    float tp = (float)t;

    float l0 = -3.4e38f, l1 = -3.4e38f;
    if (lane < cnt) {
        float d = g_center[b * NT + lo + lane] - tp;
        l0 = -(__fmul_rn(d, d)) / 10.0f;
    }
    if (lane + 32 < cnt) {
        float d = g_center[b * NT + lo + lane + 32] - tp;
        l1 = -(__fmul_rn(d, d)) / 10.0f;
    }
    float mx = fmaxf(l0, l1);
    for (int off = 16; off; off >>= 1) mx = fmaxf(mx, __shfl_xor_sync(0xffffffffu, mx, off));
    float e0 = (lane < cnt)      ? expf(l0 - mx) : 0.0f;
    float e1 = (lane + 32 < cnt) ? expf(l1 - mx) : 0.0f;
    float s = e0 + e1;
    for (int off = 16; off; off >>= 1) s += __shfl_xor_sync(0xffffffffu, s, off);
    wsm[warp][lane]      = e0 / s;
    wsm[warp][lane + 32] = e1 / s;
    __syncwarp();

    size_t wbase = ((size_t)b * NM + t) * NT;
    #pragma unroll
    for (int q = 0; q < 16; q++) {
        int p = lane + q * 32;
        int j = p - lo;
        float v = (j >= 0 && j < cnt) ? wsm[warp][j] : 0.0f;   // unmatched underflow => exact 0
        outW[wbase + p] = v;
    }

    float a[8];
    #pragma unroll
    for (int q = 0; q < 8; q++) a[q] = 0.0f;
    for (int j = 0; j < cnt; j++) {
        float wj = wsm[warp][j];
        const float* xr = x + ((size_t)b * NT + lo + j) * NH;
        #pragma unroll
        for (int q = 0; q < 8; q++) a[q] = fmaf(wj, xr[lane + q * 32], a[q]);
    }
    size_t abase = ((size_t)b * NM + t) * NH;
    #pragma unroll
    for (int q = 0; q < 8; q++) outA[abase + lane + q * 32] = a[q];
}

// ---------------- missing-word rows: block per (word,b), full 512-softmax ----------------
__global__ void attn_missing(const float* __restrict__ x,
                             float* __restrict__ outA,
                             float* __restrict__ outW)
{
    int w = blockIdx.x, b = blockIdx.y;
    if (g_phc[b * NW + w] != 0) return;
    int mc = g_melc[b * NW + w];
    if (mc == 0) return;
    int ms = g_mels[b * NW + w];

    int tid = threadIdx.x;
    int lane = tid & 31, warp = tid >> 5;
    __shared__ float wts[8][NT];
    __shared__ float cen[NT];
    __shared__ float redA[8], redB[8];

    for (int p = tid; p < NT; p += 256) cen[p] = g_center[b * NT + p];
    __syncthreads();

    for (int r0 = 0; r0 < mc; r0 += 8) {
        int RT = min(8, mc - r0);
        for (int r = 0; r < RT; r++) {
            float tp = (float)(ms + r0 + r);
            float d0 = cen[tid] - tp;
            float lg0 = -(__fmul_rn(d0, d0)) / 10.0f;
            float m0v = __fadd_rn(lg0, -1e9f);    // exact fp32 quantization as reference
            float d1 = cen[tid + 256] - tp;
            float lg1 = -(__fmul_rn(d1, d1)) / 10.0f;
            float m1v = __fadd_rn(lg1, -1e9f);

            float mx = fmaxf(m0v, m1v);
            for (int off = 16; off; off >>= 1) mx = fmaxf(mx, __shfl_xor_sync(0xffffffffu, mx, off));
            if (lane == 0) redA[warp] = mx;
            __syncthreads();
            float mall = redA[0];
            #pragma unroll
            for (int k = 1; k < 8; k++) mall = fmaxf(mall, redA[k]);

            float e0 = expf(m0v - mall);
            float e1 = expf(m1v - mall);
            float ss = e0 + e1;
            for (int off = 16; off; off >>= 1) ss += __shfl_xor_sync(0xffffffffu, ss, off);
            if (lane == 0) redB[warp] = ss;
            __syncthreads();
            float tot = redB[0];
            #pragma unroll
            for (int k = 1; k < 8; k++) tot += redB[k];

            float w0 = e0 / tot, w1 = e1 / tot;
            wts[r][tid] = w0; wts[r][tid + 256] = w1;
            size_t wb = ((size_t)b * NM + ms + r0 + r) * NT;
            outW[wb + tid] = w0; outW[wb + tid + 256] = w1;
            __syncthreads();
        }
        __syncthreads();

        float a[8];
        #pragma unroll
        for (int r = 0; r < 8; r++) a[r] = 0.0f;
        for (int p = 0; p < NT; p++) {
            float xv = x[((size_t)b * NT + p) * NH + tid];
            #pragma unroll
            for (int r = 0; r < 8; r++) a[r] = fmaf(wts[r][p], xv, a[r]);
        }
        for (int r = 0; r < RT; r++)
            outA[((size_t)b * NM + ms + r0 + r) * NH + tid] = a[r];
        __syncthreads();
    }
}

// ---------------- launcher ----------------
extern "C" void kernel_launch(void* const* d_in, const int* in_sizes, int n_in,
                              void* d_out, int out_size)
{
    const float* x       = (const float*)d_in[0];
    const float* x_mask  = (const float*)d_in[1];
    const float* pre_w1  = (const float*)d_in[2];
    const float* pre_b1  = (const float*)d_in[3];
    const float* ln1_g   = (const float*)d_in[4];
    const float* ln1_b   = (const float*)d_in[5];
    const float* pre_w2  = (const float*)d_in[6];
    const float* pre_b2  = (const float*)d_in[7];
    const float* ln2_g   = (const float*)d_in[8];
    const float* ln2_b   = (const float*)d_in[9];
    const float* proj_w  = (const float*)d_in[10];
    const float* proj_b  = (const float*)d_in[11];
    const float* gauss_w = (const float*)d_in[12];
    const float* gauss_b = (const float*)d_in[13];
    const int*   x2word  = (const int*)d_in[14];
    const int*   mel2word= (const int*)d_in[15];

    float* outA  = (float*)d_out;                                  // (8,4096,256)
    float* outW  = outA + (size_t)NB * NM * NH;                    // (8,4096,512)
    float* outMW = outW + (size_t)NB * NM * NT;                    // (8,256)

    float* h1; cudaGetSymbolAddress((void**)&h1, g_h1);
    float* h2; cudaGetSymbolAddress((void**)&h2, g_h2);

    conv_ln_relu<<<NB * (NT / 32), 256>>>(x,  x_mask, pre_w1, pre_b1, ln1_g, ln1_b, h1);
    conv_ln_relu<<<NB * (NT / 32), 256>>>(h1, x_mask, pre_w2, pre_b2, ln2_g, ln2_b, h2);
    proj_gauss  <<<NB * (NT / 16), 256>>>(x, x_mask, proj_w, proj_b, gauss_w, gauss_b);
    stats_kernel<<<NB, 256>>>(x2word, mel2word, outMW);
    attn_matched<<<NB * NM / 8, 256>>>(x, mel2word, outA, outW);
    attn_missing<<<dim3(NW, NB), 256>>>(x, outA, outW);
}